// round 2
// baseline (speedup 1.0000x reference)
#include <cuda_runtime.h>

#define NROWS  16384
#define NFEATD 256
#define NEMBD  128

// ---------------- scratch (no allocations allowed) ----------------
__device__ float g_neigh[NROWS * NFEATD];   // raw adj @ x (pre-division)
__device__ float g_deg[NROWS];              // rowsum(adj) + 1

// ---------------- Kernel A: neigh_raw = adj @ x, deg = rowsum+1 ----
#define BM 128
#define BN 64
#define BK 16

__global__ __launch_bounds__(128)
void gemm_adj(const float* __restrict__ A, const float* __restrict__ X) {
    __shared__ float As[BK][BM + 4];   // transposed A tile, padded
    __shared__ float Bs[BK][BN];

    const int tid  = threadIdx.x;          // 0..127
    const int cRow = blockIdx.y * BM;
    const int cCol = blockIdx.x * BN;
    const int tx   = tid & 7;              // 0..7  -> 8 cols each
    const int ty   = tid >> 3;             // 0..15 -> 8 rows each

    float acc[8][8];
#pragma unroll
    for (int i = 0; i < 8; i++)
#pragma unroll
        for (int j = 0; j < 8; j++) acc[i][j] = 0.f;

    float degacc = 0.f;
    const bool do_deg = (blockIdx.x == 0);

    for (int k0 = 0; k0 < NROWS; k0 += BK) {
        // Load A tile (128 x 16) -> As transposed. 512 float4, 4 per thread.
#pragma unroll
        for (int i = 0; i < 4; i++) {
            int idx = tid + 128 * i;                 // 0..511
            int r = idx >> 2;
            int c = (idx & 3) * 4;
            const float4 av = *reinterpret_cast<const float4*>(
                A + (size_t)(cRow + r) * NROWS + k0 + c);
            As[c + 0][r] = av.x;
            As[c + 1][r] = av.y;
            As[c + 2][r] = av.z;
            As[c + 3][r] = av.w;
        }
        // Load B tile (16 x 64). 256 float4, 2 per thread.
#pragma unroll
        for (int i = 0; i < 2; i++) {
            int idx = tid + 128 * i;                 // 0..255
            int r = idx >> 4;
            int c = (idx & 15) * 4;
            *reinterpret_cast<float4*>(&Bs[r][c]) =
                *reinterpret_cast<const float4*>(
                    X + (size_t)(k0 + r) * NFEATD + cCol + c);
        }
        __syncthreads();

        if (do_deg) {
#pragma unroll
            for (int kk = 0; kk < BK; kk++) degacc += As[kk][tid];
        }

#pragma unroll
        for (int kk = 0; kk < BK; kk++) {
            float4 a0  = *reinterpret_cast<const float4*>(&As[kk][ty * 8]);
            float4 a1  = *reinterpret_cast<const float4*>(&As[kk][ty * 8 + 4]);
            float4 bb0 = *reinterpret_cast<const float4*>(&Bs[kk][tx * 8]);
            float4 bb1 = *reinterpret_cast<const float4*>(&Bs[kk][tx * 8 + 4]);
            float a[8] = {a0.x, a0.y, a0.z, a0.w, a1.x, a1.y, a1.z, a1.w};
            float b[8] = {bb0.x, bb0.y, bb0.z, bb0.w, bb1.x, bb1.y, bb1.z, bb1.w};
#pragma unroll
            for (int i = 0; i < 8; i++)
#pragma unroll
                for (int j = 0; j < 8; j++) acc[i][j] += a[i] * b[j];
        }
        __syncthreads();
    }

#pragma unroll
    for (int i = 0; i < 8; i++) {
        int r = cRow + ty * 8 + i;
#pragma unroll
        for (int j = 0; j < 8; j += 4) {
            float4 v = make_float4(acc[i][j], acc[i][j + 1], acc[i][j + 2], acc[i][j + 3]);
            *reinterpret_cast<float4*>(g_neigh + (size_t)r * NFEATD + cCol + tx * 8 + j) = v;
        }
    }
    if (do_deg) g_deg[cRow + tid] = degacc + 1.0f;
}

// ---------------- Kernel B: fused proj + MLP + softmax --------------
// 8 rows per block, 128 threads. smem pool reused across stages.
__global__ __launch_bounds__(128)
void mlp_kernel(const float* __restrict__ x,
                const float* __restrict__ Wp,
                const float* __restrict__ W1, const float* __restrict__ b1,
                const float* __restrict__ W2, const float* __restrict__ b2,
                const float* __restrict__ W3, const float* __restrict__ b3,
                float* __restrict__ out) {
    __shared__ float pool[10120];
    // stage-1 layout
    const int V_OFF   = 0;       // 8 x 512 = 4096 floats (concat [x | neigh])
    const int WS_OFF  = 4096;    // 128 x 33 = 4224 floats (Wp chunk, padded)
    const int HS_OFF  = 8320;    // 8 x 128  = 1024 floats (relu(proj))
    const int H1_OFF  = 9344;    // 8 x 64   = 512
    const int H2_OFF  = 9856;    // 8 x 32   = 256
    const int DEG_OFF = 10112;   // 8
    // stage-2 reuse of [0, 8320)
    const int W1S_OFF = 0;       // 128 x 64 transposed = 8192
    const int W2S_OFF = 0;       // 64 x 32 transposed  = 2048
    const int W3S_OFF = 2048;    // 32 x 8 transposed   = 256

    const int tid  = threadIdx.x;
    const int row0 = blockIdx.x * 8;

    if (tid < 8) pool[DEG_OFF + tid] = 1.0f / g_deg[row0 + tid];
    __syncthreads();

    // v = [x_row | neigh_raw_row / deg]
    for (int idx = tid; idx < 4096; idx += 128) {
        int r = idx >> 9, c = idx & 511;
        int row = row0 + r;
        float val;
        if (c < 256) val = x[row * 256 + c];
        else         val = g_neigh[row * 256 + (c - 256)] * pool[DEG_OFF + r];
        pool[V_OFF + idx] = val;
    }
    __syncthreads();

    // stage 1: h[r][tid] = relu( sum_k Wp[tid][k] * v[r][k] ), k over 512
    float acc[8];
#pragma unroll
    for (int r = 0; r < 8; r++) acc[r] = 0.f;

    for (int kc = 0; kc < 16; kc++) {
        // stage a 128x32 chunk of Wp into padded smem
        for (int i = 0; i < 32; i++) {
            int idx = tid + 128 * i;           // 0..4095
            int rr = idx >> 5, cc = idx & 31;
            pool[WS_OFF + rr * 33 + cc] = Wp[rr * 512 + kc * 32 + cc];
        }
        __syncthreads();

        float w[32];
#pragma unroll
        for (int k = 0; k < 32; k++) w[k] = pool[WS_OFF + tid * 33 + k];

#pragma unroll
        for (int r = 0; r < 8; r++) {
            const float* vb = &pool[V_OFF + r * 512 + kc * 32];
#pragma unroll
            for (int k = 0; k < 32; k += 4) {
                float4 vv = *reinterpret_cast<const float4*>(vb + k);
                acc[r] += w[k + 0] * vv.x + w[k + 1] * vv.y
                        + w[k + 2] * vv.z + w[k + 3] * vv.w;
            }
        }
        __syncthreads();
    }
#pragma unroll
    for (int r = 0; r < 8; r++) pool[HS_OFF + r * 128 + tid] = fmaxf(acc[r], 0.f);
    __syncthreads();

    // stage W1 transposed: W1s[k*64 + j] = W1[j*128 + k]
    for (int idx = tid; idx < 8192; idx += 128) {
        int j = idx >> 7, k = idx & 127;
        pool[W1S_OFF + k * 64 + j] = W1[idx];
    }
    __syncthreads();

    // MLP1: 8x64 outputs
#pragma unroll
    for (int ii = 0; ii < 4; ii++) {
        int idx = tid + 128 * ii;
        int r = idx >> 6, j = idx & 63;
        float a = b1[j];
#pragma unroll 8
        for (int k = 0; k < 128; k++)
            a += pool[W1S_OFF + k * 64 + j] * pool[HS_OFF + r * 128 + k];
        pool[H1_OFF + r * 64 + j] = (a > 0.f) ? a : 0.01f * a;
    }
    __syncthreads();

    // stage W2, W3 transposed (overwrites W1s region)
    for (int idx = tid; idx < 2048; idx += 128) {
        int j = idx >> 6, k = idx & 63;
        pool[W2S_OFF + k * 32 + j] = W2[idx];
    }
    for (int idx = tid; idx < 256; idx += 128) {
        int j = idx >> 5, k = idx & 31;
        pool[W3S_OFF + k * 8 + j] = W3[idx];
    }
    __syncthreads();

    // MLP2: 8x32 outputs
#pragma unroll
    for (int ii = 0; ii < 2; ii++) {
        int idx = tid + 128 * ii;
        int r = idx >> 5, j = idx & 31;
        float a = b2[j];
#pragma unroll 8
        for (int k = 0; k < 64; k++)
            a += pool[W2S_OFF + k * 32 + j] * pool[H1_OFF + r * 64 + k];
        pool[H2_OFF + r * 32 + j] = (a > 0.f) ? a : 0.01f * a;
    }
    __syncthreads();

    // MLP3: 8x8 outputs -> reuse H1 region
    if (tid < 64) {
        int r = tid >> 3, j = tid & 7;
        float a = b3[j];
#pragma unroll
        for (int k = 0; k < 32; k++)
            a += pool[W3S_OFF + k * 8 + j] * pool[H2_OFF + r * 32 + k];
        pool[H1_OFF + r * 8 + j] = (a > 0.f) ? a : 0.01f * a;
    }
    __syncthreads();

    // softmax over 8 logits per row
    if (tid < 8) {
        int r = tid;
        float vv[8];
        float m = -1e30f;
#pragma unroll
        for (int c = 0; c < 8; c++) {
            vv[c] = pool[H1_OFF + r * 8 + c];
            m = fmaxf(m, vv[c]);
        }
        float s = 0.f;
#pragma unroll
        for (int c = 0; c < 8; c++) { vv[c] = expf(vv[c] - m); s += vv[c]; }
        float inv = 1.0f / s;
#pragma unroll
        for (int c = 0; c < 8; c++) out[(row0 + r) * 8 + c] = vv[c] * inv;
    }
}

// ---------------- launch ----------------
extern "C" void kernel_launch(void* const* d_in, const int* in_sizes, int n_in,
                              void* d_out, int out_size) {
    const float* x   = (const float*)d_in[0];
    const float* adj = (const float*)d_in[1];
    const float* Wp  = (const float*)d_in[2];
    const float* W1  = (const float*)d_in[3];
    const float* b1  = (const float*)d_in[4];
    const float* W2  = (const float*)d_in[5];
    const float* b2  = (const float*)d_in[6];
    const float* W3  = (const float*)d_in[7];
    const float* b3  = (const float*)d_in[8];
    float* out = (float*)d_out;

    dim3 gridA(NFEATD / BN, NROWS / BM);   // (4, 128)
    gemm_adj<<<gridA, 128>>>(adj, x);

    mlp_kernel<<<NROWS / 8, 128>>>(x, Wp, W1, b1, W2, b2, W3, b3, out);
}

// round 4
// speedup vs baseline: 4.1481x; 4.1481x over previous
#include <cuda_runtime.h>
#include <cstdint>

#define NROWS  16384
#define NFEATD 256
#define NITER  512          // 16384 / 32
#define BM 256
#define BN 128
#define BK 32
#define STAGES 3
#define APITCH 36           // floats per A row (padded)
#define BPITCH 36
#define A_FLOATS (BM * APITCH)          // 9216
#define B_FLOATS (BN * BPITCH)          // 4608
#define STAGE_FLOATS (A_FLOATS + B_FLOATS)  // 13824

// ---------------- scratch (no allocations allowed) ----------------
__device__ float g_neigh[NROWS * NFEATD];
__device__ float g_deg[NROWS];
__device__ float g_xT[NFEATD * NROWS];

__device__ __forceinline__ uint32_t cvta_smem(const void* p) {
    uint32_t a;
    asm("{ .reg .u64 t; cvta.to.shared.u64 t, %1; cvt.u32.u64 %0, t; }"
        : "=r"(a) : "l"(p));
    return a;
}
__device__ __forceinline__ void cp16(uint32_t saddr, const void* gaddr) {
    asm volatile("cp.async.cg.shared.global [%0], [%1], 16;"
                 :: "r"(saddr), "l"(gaddr));
}
__device__ __forceinline__ void mma_tf32(float& d0, float& d1, float& d2, float& d3,
                                         uint32_t a0, uint32_t a1, uint32_t a2, uint32_t a3,
                                         uint32_t b0, uint32_t b1) {
    asm volatile(
        "mma.sync.aligned.m16n8k8.row.col.f32.tf32.tf32.f32 "
        "{%0,%1,%2,%3}, {%4,%5,%6,%7}, {%8,%9}, {%0,%1,%2,%3};"
        : "+f"(d0), "+f"(d1), "+f"(d2), "+f"(d3)
        : "r"(a0), "r"(a1), "r"(a2), "r"(a3), "r"(b0), "r"(b1));
}

// ---------------- Kernel 0: transpose x -> g_xT ----------------
__global__ __launch_bounds__(256)
void transpose_x(const float* __restrict__ x) {
    __shared__ float t[32][33];
    int r0 = blockIdx.x * 32;
    int c0 = blockIdx.y * 32;
    int tx = threadIdx.x, ty = threadIdx.y;
#pragma unroll
    for (int i = ty; i < 32; i += 8)
        t[i][tx] = x[(size_t)(r0 + i) * NFEATD + c0 + tx];
    __syncthreads();
#pragma unroll
    for (int i = ty; i < 32; i += 8)
        g_xT[(size_t)(c0 + i) * NROWS + r0 + tx] = t[tx][i];
}

// ---------------- Kernel A: tf32 mma.sync GEMM  g_neigh = adj @ x ----
// grid (64, 2): BM=256 rows x BN=128 cols per CTA. 256 threads, 8 warps (2M x 4N... -> 4M x 2N? )
// warp grid: 4 (M) x 2 (N) -> warp tile 64 x 64.

__device__ __forceinline__ void load_tile(int i, uint32_t smem, const float* __restrict__ adj,
                                          int m0, int n0, int tid) {
    int s = i % STAGES;
    uint32_t As = smem + s * (STAGE_FLOATS * 4);
    uint32_t Bs = As + A_FLOATS * 4;
    int k0 = i * BK;
    // A: 256 rows x 8 chunks = 2048 chunks, 8 per thread
#pragma unroll
    for (int c = 0; c < 8; c++) {
        int q = c * 256 + tid;
        int r = q >> 3, cb = q & 7;
        cp16(As + r * (APITCH * 4) + cb * 16,
             adj + (size_t)(m0 + r) * NROWS + k0 + cb * 4);
    }
    // B: 128 rows x 8 chunks = 1024 chunks, 4 per thread
#pragma unroll
    for (int c = 0; c < 4; c++) {
        int q = c * 256 + tid;
        int r = q >> 3, cb = q & 7;
        cp16(Bs + r * (BPITCH * 4) + cb * 16,
             g_xT + (size_t)(n0 + r) * NROWS + k0 + cb * 4);
    }
    asm volatile("cp.async.commit_group;" ::: "memory");
}

__global__ __launch_bounds__(256, 1)
void gemm_mma(const float* __restrict__ adj) {
    extern __shared__ float sm[];
    const int tid  = threadIdx.x;
    const int wid  = tid >> 5;
    const int lane = tid & 31;
    const int wm   = wid >> 1;            // 0..3  (M)
    const int wn   = wid & 1;             // 0..1  (N)
    const int m0   = blockIdx.x * BM;
    const int n0   = blockIdx.y * BN;
    const bool do_deg = (blockIdx.y == 0);

    uint32_t smem = cvta_smem(sm);

    float acc[4][8][4];
#pragma unroll
    for (int i = 0; i < 4; i++)
#pragma unroll
        for (int j = 0; j < 8; j++)
#pragma unroll
            for (int v = 0; v < 4; v++) acc[i][j][v] = 0.f;

#pragma unroll
    for (int i = 0; i < STAGES; i++) load_tile(i, smem, adj, m0, n0, tid);

    float degacc = 0.f;
    const int lq = lane >> 2;   // lane/4
    const int lr = lane & 3;    // lane%4

#pragma unroll 1
    for (int i = 0; i < NITER; i++) {
        int s = i % STAGES;
        int rem = (NITER - 1) - i;
        if (rem >= 2)      asm volatile("cp.async.wait_group 2;" ::: "memory");
        else if (rem == 1) asm volatile("cp.async.wait_group 1;" ::: "memory");
        else               asm volatile("cp.async.wait_group 0;" ::: "memory");
        __syncthreads();

        const float* As = sm + s * STAGE_FLOATS;
        const float* Bs = As + A_FLOATS;

#pragma unroll
        for (int ks = 0; ks < 4; ks++) {
            // load fragments
            uint32_t af[4][4];
#pragma unroll
            for (int mt = 0; mt < 4; mt++) {
                int rb = wm * 64 + mt * 16 + lq;
                int cb = ks * 8 + lr;
                af[mt][0] = __float_as_uint(As[rb * APITCH + cb]);
                af[mt][1] = __float_as_uint(As[(rb + 8) * APITCH + cb]);
                af[mt][2] = __float_as_uint(As[rb * APITCH + cb + 4]);
                af[mt][3] = __float_as_uint(As[(rb + 8) * APITCH + cb + 4]);
            }
            uint32_t bf[8][2];
#pragma unroll
            for (int nt = 0; nt < 8; nt++) {
                int nb = wn * 64 + nt * 8 + lq;
                int kb = ks * 8 + lr;
                bf[nt][0] = __float_as_uint(Bs[nb * BPITCH + kb]);
                bf[nt][1] = __float_as_uint(Bs[nb * BPITCH + kb + 4]);
            }
#pragma unroll
            for (int mt = 0; mt < 4; mt++)
#pragma unroll
                for (int nt = 0; nt < 8; nt++)
                    mma_tf32(acc[mt][nt][0], acc[mt][nt][1], acc[mt][nt][2], acc[mt][nt][3],
                             af[mt][0], af[mt][1], af[mt][2], af[mt][3],
                             bf[nt][0], bf[nt][1]);
        }

        if (do_deg) {
            // thread tid sums A row tid of this stage (pitch 36 floats, 16B aligned)
#pragma unroll
            for (int cb = 0; cb < 8; cb++) {
                float4 v = *reinterpret_cast<const float4*>(&As[tid * APITCH + cb * 4]);
                degacc += (v.x + v.y) + (v.z + v.w);
            }
        }
        __syncthreads();

        if (i + STAGES < NITER) load_tile(i + STAGES, smem, adj, m0, n0, tid);
    }

    if (do_deg) g_deg[m0 + tid] = degacc + 1.0f;

    // epilogue: c0,c1 at (r, c), c2,c3 at (r+8, c); c = 2*(lane%4)
#pragma unroll
    for (int mt = 0; mt < 4; mt++) {
#pragma unroll
        for (int nt = 0; nt < 8; nt++) {
            int r = m0 + wm * 64 + mt * 16 + lq;
            int c = n0 + wn * 64 + nt * 8 + lr * 2;
            float2 v0 = make_float2(acc[mt][nt][0], acc[mt][nt][1]);
            float2 v1 = make_float2(acc[mt][nt][2], acc[mt][nt][3]);
            *reinterpret_cast<float2*>(g_neigh + (size_t)r * NFEATD + c) = v0;
            *reinterpret_cast<float2*>(g_neigh + (size_t)(r + 8) * NFEATD + c) = v1;
        }
    }
}

// ---------------- Kernel B: fused proj + MLP + softmax ----
__global__ __launch_bounds__(128)
void mlp_kernel(const float* __restrict__ x,
                const float* __restrict__ Wp,
                const float* __restrict__ W1, const float* __restrict__ b1,
                const float* __restrict__ W2, const float* __restrict__ b2,
                const float* __restrict__ W3, const float* __restrict__ b3,
                float* __restrict__ out) {
    __shared__ float pool[10120];
    const int V_OFF   = 0;
    const int WS_OFF  = 4096;
    const int HS_OFF  = 8320;
    const int H1_OFF  = 9344;
    const int H2_OFF  = 9856;
    const int DEG_OFF = 10112;
    const int W1S_OFF = 0;
    const int W2S_OFF = 0;
    const int W3S_OFF = 2048;

    const int tid  = threadIdx.x;
    const int row0 = blockIdx.x * 8;

    if (tid < 8) pool[DEG_OFF + tid] = 1.0f / g_deg[row0 + tid];
    __syncthreads();

    for (int idx = tid; idx < 4096; idx += 128) {
        int r = idx >> 9, c = idx & 511;
        int row = row0 + r;
        float val;
        if (c < 256) val = x[row * 256 + c];
        else         val = g_neigh[row * 256 + (c - 256)] * pool[DEG_OFF + r];
        pool[V_OFF + idx] = val;
    }
    __syncthreads();

    float acc[8];
#pragma unroll
    for (int r = 0; r < 8; r++) acc[r] = 0.f;

    for (int kc = 0; kc < 16; kc++) {
        for (int i = 0; i < 32; i++) {
            int idx = tid + 128 * i;
            int rr = idx >> 5, cc = idx & 31;
            pool[WS_OFF + rr * 33 + cc] = Wp[rr * 512 + kc * 32 + cc];
        }
        __syncthreads();

        float w[32];
#pragma unroll
        for (int k = 0; k < 32; k++) w[k] = pool[WS_OFF + tid * 33 + k];

#pragma unroll
        for (int r = 0; r < 8; r++) {
            const float* vb = &pool[V_OFF + r * 512 + kc * 32];
#pragma unroll
            for (int k = 0; k < 32; k += 4) {
                float4 vv = *reinterpret_cast<const float4*>(vb + k);
                acc[r] += w[k + 0] * vv.x + w[k + 1] * vv.y
                        + w[k + 2] * vv.z + w[k + 3] * vv.w;
            }
        }
        __syncthreads();
    }
#pragma unroll
    for (int r = 0; r < 8; r++) pool[HS_OFF + r * 128 + tid] = fmaxf(acc[r], 0.f);
    __syncthreads();

    for (int idx = tid; idx < 8192; idx += 128) {
        int j = idx >> 7, k = idx & 127;
        pool[W1S_OFF + k * 64 + j] = W1[idx];
    }
    __syncthreads();

#pragma unroll
    for (int ii = 0; ii < 4; ii++) {
        int idx = tid + 128 * ii;
        int r = idx >> 6, j = idx & 63;
        float a = b1[j];
#pragma unroll 8
        for (int k = 0; k < 128; k++)
            a += pool[W1S_OFF + k * 64 + j] * pool[HS_OFF + r * 128 + k];
        pool[H1_OFF + r * 64 + j] = (a > 0.f) ? a : 0.01f * a;
    }
    __syncthreads();

    for (int idx = tid; idx < 2048; idx += 128) {
        int j = idx >> 6, k = idx & 63;
        pool[W2S_OFF + k * 32 + j] = W2[idx];
    }
    for (int idx = tid; idx < 256; idx += 128) {
        int j = idx >> 5, k = idx & 31;
        pool[W3S_OFF + k * 8 + j] = W3[idx];
    }
    __syncthreads();

#pragma unroll
    for (int ii = 0; ii < 2; ii++) {
        int idx = tid + 128 * ii;
        int r = idx >> 5, j = idx & 31;
        float a = b2[j];
#pragma unroll 8
        for (int k = 0; k < 64; k++)
            a += pool[W2S_OFF + k * 32 + j] * pool[H1_OFF + r * 64 + k];
        pool[H2_OFF + r * 32 + j] = (a > 0.f) ? a : 0.01f * a;
    }
    __syncthreads();

    if (tid < 64) {
        int r = tid >> 3, j = tid & 7;
        float a = b3[j];
#pragma unroll
        for (int k = 0; k < 32; k++)
            a += pool[W3S_OFF + k * 8 + j] * pool[H2_OFF + r * 32 + k];
        pool[H1_OFF + r * 8 + j] = (a > 0.f) ? a : 0.01f * a;
    }
    __syncthreads();

    if (tid < 8) {
        int r = tid;
        float vv[8];
        float m = -1e30f;
#pragma unroll
        for (int c = 0; c < 8; c++) {
            vv[c] = pool[H1_OFF + r * 8 + c];
            m = fmaxf(m, vv[c]);
        }
        float s = 0.f;
#pragma unroll
        for (int c = 0; c < 8; c++) { vv[c] = expf(vv[c] - m); s += vv[c]; }
        float inv = 1.0f / s;
#pragma unroll
        for (int c = 0; c < 8; c++) out[(row0 + r) * 8 + c] = vv[c] * inv;
    }
}

// ---------------- launch ----------------
extern "C" void kernel_launch(void* const* d_in, const int* in_sizes, int n_in,
                              void* d_out, int out_size) {
    const float* x   = (const float*)d_in[0];
    const float* adj = (const float*)d_in[1];
    const float* Wp  = (const float*)d_in[2];
    const float* W1  = (const float*)d_in[3];
    const float* b1  = (const float*)d_in[4];
    const float* W2  = (const float*)d_in[5];
    const float* b2  = (const float*)d_in[6];
    const float* W3  = (const float*)d_in[7];
    const float* b3  = (const float*)d_in[8];
    float* out = (float*)d_out;

    const int smem_bytes = STAGES * STAGE_FLOATS * 4;   // 165888
    cudaFuncSetAttribute(gemm_mma, cudaFuncAttributeMaxDynamicSharedMemorySize, smem_bytes);

    dim3 gridT(NROWS / 32, NFEATD / 32);
    transpose_x<<<gridT, dim3(32, 8)>>>(x);

    dim3 gridG(NROWS / BM, NFEATD / BN);   // (64, 2)
    gemm_mma<<<gridG, 256, smem_bytes>>>(adj);

    mlp_kernel<<<NROWS / 8, 128>>>(x, Wp, W1, b1, W2, b2, W3, b3, out);
}

// round 5
// speedup vs baseline: 6.2020x; 1.4951x over previous
#include <cuda_runtime.h>
#include <cuda_fp16.h>
#include <cstdint>

#define NROWS  16384
#define NFEATD 256
#define BMh 128
#define BKh 32                    // K floats per iter
#define NITERh 512                // 16384/32
#define APITCH 20                 // u32 per A row (16 data + 4 pad)
#define BPITCH 20
#define A_STAGE (128 * APITCH)    // 2560 u32
#define B_STAGE (256 * BPITCH)    // 5120 u32

// ---------------- scratch ----------------
__device__ float  g_neigh[NROWS * NFEATD];
__device__ float  g_deg[NROWS];
__device__ __half g_xTh[NFEATD * NROWS];    // x transposed, fp16

__device__ __forceinline__ void cp16(uint32_t saddr, const void* gaddr) {
    asm volatile("cp.async.cg.shared.global [%0], [%1], 16;"
                 :: "r"(saddr), "l"(gaddr));
}
__device__ __forceinline__ uint32_t cvta_smem(const void* p) {
    uint32_t a;
    asm("{ .reg .u64 t; cvta.to.shared.u64 t, %1; cvt.u32.u64 %0, t; }"
        : "=r"(a) : "l"(p));
    return a;
}
__device__ __forceinline__ void mma_f16(float& d0, float& d1, float& d2, float& d3,
                                        uint32_t a0, uint32_t a1, uint32_t a2, uint32_t a3,
                                        uint32_t b0, uint32_t b1) {
    asm volatile(
        "mma.sync.aligned.m16n8k16.row.col.f32.f16.f16.f32 "
        "{%0,%1,%2,%3}, {%4,%5,%6,%7}, {%8,%9}, {%0,%1,%2,%3};"
        : "+f"(d0), "+f"(d1), "+f"(d2), "+f"(d3)
        : "r"(a0), "r"(a1), "r"(a2), "r"(a3), "r"(b0), "r"(b1));
}
__device__ __forceinline__ uint32_t h2u(__half2 h) {
    return *reinterpret_cast<uint32_t*>(&h);
}

// ---------------- Kernel 0: transpose x -> g_xTh (fp16) ----------------
__global__ __launch_bounds__(256)
void transpose_x(const float* __restrict__ x) {
    __shared__ float t[32][33];
    int r0 = blockIdx.x * 32;
    int c0 = blockIdx.y * 32;
    int tx = threadIdx.x, ty = threadIdx.y;
#pragma unroll
    for (int i = ty; i < 32; i += 8)
        t[i][tx] = x[(size_t)(r0 + i) * NFEATD + c0 + tx];
    __syncthreads();
#pragma unroll
    for (int i = ty; i < 32; i += 8)
        g_xTh[(size_t)(c0 + i) * NROWS + r0 + tx] = __float2half_rn(t[tx][i]);
}

// ---------------- Kernel A: fp16 mma GEMM  g_neigh = adj @ x ----------
// grid = 128 CTAs (BM=128 rows each, full N=256). 512 threads = 16 warps.
// warp tile 32(M) x 64(N). adj converted fp32->fp16 in-kernel; deg fused.

__device__ __forceinline__ void load_B(int s, int k0, uint32_t bbase, int tid) {
    // B tile: 256 n-rows x 32 halves (64B) each, pitch 80B. 1024 cp16.
#pragma unroll
    for (int j = 0; j < 2; j++) {
        int q  = tid + 512 * j;
        int n  = q >> 2;
        int cc = q & 3;
        cp16(bbase + s * (B_STAGE * 4) + n * 80 + cc * 16,
             g_xTh + (size_t)n * NROWS + k0 + cc * 8);
    }
    asm volatile("cp.async.commit_group;" ::: "memory");
}

__global__ __launch_bounds__(512, 1)
void gemm_h(const float* __restrict__ adj) {
    extern __shared__ uint32_t smh[];
    uint32_t* Abuf = smh;                       // 2 stages
    uint32_t* Bbuf = smh + 2 * A_STAGE;         // 3 stages

    const int tid  = threadIdx.x;
    const int wid  = tid >> 5;
    const int lane = tid & 31;
    const int lq   = lane >> 2;    // 0..7
    const int lr   = lane & 3;     // 0..3
    const int gg   = lane >> 3;    // 0..3 (A-load row group)
    const int cc   = lane & 7;     // 0..7 (A-load col chunk)
    const int wm   = wid & 3;      // M warp 0..3 (32 rows each)
    const int wn   = wid >> 2;     // N warp 0..3 (64 cols each)
    const int m0   = blockIdx.x * BMh;

    const uint32_t bbase = cvta_smem(Bbuf);

    float acc[2][8][4];
#pragma unroll
    for (int i = 0; i < 2; i++)
#pragma unroll
        for (int j = 0; j < 8; j++)
#pragma unroll
            for (int v = 0; v < 4; v++) acc[i][j][v] = 0.f;

    // prologue: B stages 0..2
#pragma unroll
    for (int s = 0; s < 3; s++) load_B(s, s * BKh, bbase, tid);

    // A iter0 -> regs (2 passes x float4; rows fixed per thread)
    const int rowA0 = wid * 8 + gg;       // pass p adds p*4
    float4 areg[2];
#pragma unroll
    for (int p = 0; p < 2; p++)
        areg[p] = *reinterpret_cast<const float4*>(
            adj + (size_t)(m0 + rowA0 + p * 4) * NROWS + cc * 4);

    float degp[2] = {0.f, 0.f};

#pragma unroll 1
    for (int i = 0; i < NITERh; i++) {
        const int sA = i & 1;
        const int sB = i % 3;

        // STS A(i) fp16 + deg accumulation
#pragma unroll
        for (int p = 0; p < 2; p++) {
            float4 v = areg[p];
            degp[p] += (v.x + v.y) + (v.z + v.w);
            uint32_t h0 = h2u(__floats2half2_rn(v.x, v.y));
            uint32_t h1 = h2u(__floats2half2_rn(v.z, v.w));
            uint32_t* dst = Abuf + sA * A_STAGE + (rowA0 + p * 4) * APITCH + cc * 2;
            dst[0] = h0;
            dst[1] = h1;
        }
        // LDG A(i+1)
        if (i + 1 < NITERh) {
            int k0n = (i + 1) * BKh;
#pragma unroll
            for (int p = 0; p < 2; p++)
                areg[p] = *reinterpret_cast<const float4*>(
                    adj + (size_t)(m0 + rowA0 + p * 4) * NROWS + k0n + cc * 4);
        }

        // wait for B(i)
        int rem = (NITERh - 1) - i;
        if (rem >= 2)      asm volatile("cp.async.wait_group 2;" ::: "memory");
        else if (rem == 1) asm volatile("cp.async.wait_group 1;" ::: "memory");
        else               asm volatile("cp.async.wait_group 0;" ::: "memory");
        __syncthreads();

        const uint32_t* As = Abuf + sA * A_STAGE;
        const uint32_t* Bs = Bbuf + sB * B_STAGE;

#pragma unroll
        for (int ks = 0; ks < 2; ks++) {
            uint32_t af[2][4];
#pragma unroll
            for (int mt = 0; mt < 2; mt++) {
                int r = wm * 32 + mt * 16 + lq;
                int b = r * APITCH + ks * 8 + lr;
                af[mt][0] = As[b];
                af[mt][1] = As[b + 8 * APITCH];
                af[mt][2] = As[b + 4];
                af[mt][3] = As[b + 8 * APITCH + 4];
            }
            uint32_t bf[8][2];
#pragma unroll
            for (int nt = 0; nt < 8; nt++) {
                int n = wn * 64 + nt * 8 + lq;
                int b = n * BPITCH + ks * 8 + lr;
                bf[nt][0] = Bs[b];
                bf[nt][1] = Bs[b + 4];
            }
#pragma unroll
            for (int mt = 0; mt < 2; mt++)
#pragma unroll
                for (int nt = 0; nt < 8; nt++)
                    mma_f16(acc[mt][nt][0], acc[mt][nt][1], acc[mt][nt][2], acc[mt][nt][3],
                            af[mt][0], af[mt][1], af[mt][2], af[mt][3],
                            bf[nt][0], bf[nt][1]);
        }
        __syncthreads();

        if (i + 3 < NITERh) load_B((i + 3) % 3, (i + 3) * BKh, bbase, tid);
    }

    // deg: reduce over 8-lane groups (cc), lane cc==0 writes
#pragma unroll
    for (int p = 0; p < 2; p++) {
        float d = degp[p];
#pragma unroll
        for (int off = 1; off < 8; off <<= 1)
            d += __shfl_xor_sync(0xffffffffu, d, off);
        if (cc == 0) g_deg[m0 + rowA0 + p * 4] = d + 1.0f;
    }

    // epilogue
#pragma unroll
    for (int mt = 0; mt < 2; mt++) {
#pragma unroll
        for (int nt = 0; nt < 8; nt++) {
            int r = m0 + wm * 32 + mt * 16 + lq;
            int c = wn * 64 + nt * 8 + lr * 2;
            *reinterpret_cast<float2*>(g_neigh + (size_t)r * NFEATD + c) =
                make_float2(acc[mt][nt][0], acc[mt][nt][1]);
            *reinterpret_cast<float2*>(g_neigh + (size_t)(r + 8) * NFEATD + c) =
                make_float2(acc[mt][nt][2], acc[mt][nt][3]);
        }
    }
}

// ---------------- Kernel B: fused proj + MLP + softmax (unchanged) ----
__global__ __launch_bounds__(128)
void mlp_kernel(const float* __restrict__ x,
                const float* __restrict__ Wp,
                const float* __restrict__ W1, const float* __restrict__ b1,
                const float* __restrict__ W2, const float* __restrict__ b2,
                const float* __restrict__ W3, const float* __restrict__ b3,
                float* __restrict__ out) {
    __shared__ float pool[10120];
    const int V_OFF   = 0;
    const int WS_OFF  = 4096;
    const int HS_OFF  = 8320;
    const int H1_OFF  = 9344;
    const int H2_OFF  = 9856;
    const int DEG_OFF = 10112;
    const int W1S_OFF = 0;
    const int W2S_OFF = 0;
    const int W3S_OFF = 2048;

    const int tid  = threadIdx.x;
    const int row0 = blockIdx.x * 8;

    if (tid < 8) pool[DEG_OFF + tid] = 1.0f / g_deg[row0 + tid];
    __syncthreads();

    for (int idx = tid; idx < 4096; idx += 128) {
        int r = idx >> 9, c = idx & 511;
        int row = row0 + r;
        float val;
        if (c < 256) val = x[row * 256 + c];
        else         val = g_neigh[row * 256 + (c - 256)] * pool[DEG_OFF + r];
        pool[V_OFF + idx] = val;
    }
    __syncthreads();

    float acc[8];
#pragma unroll
    for (int r = 0; r < 8; r++) acc[r] = 0.f;

    for (int kc = 0; kc < 16; kc++) {
        for (int i = 0; i < 32; i++) {
            int idx = tid + 128 * i;
            int rr = idx >> 5, ccx = idx & 31;
            pool[WS_OFF + rr * 33 + ccx] = Wp[rr * 512 + kc * 32 + ccx];
        }
        __syncthreads();

        float w[32];
#pragma unroll
        for (int k = 0; k < 32; k++) w[k] = pool[WS_OFF + tid * 33 + k];

#pragma unroll
        for (int r = 0; r < 8; r++) {
            const float* vb = &pool[V_OFF + r * 512 + kc * 32];
#pragma unroll
            for (int k = 0; k < 32; k += 4) {
                float4 vv = *reinterpret_cast<const float4*>(vb + k);
                acc[r] += w[k + 0] * vv.x + w[k + 1] * vv.y
                        + w[k + 2] * vv.z + w[k + 3] * vv.w;
            }
        }
        __syncthreads();
    }
#pragma unroll
    for (int r = 0; r < 8; r++) pool[HS_OFF + r * 128 + tid] = fmaxf(acc[r], 0.f);
    __syncthreads();

    for (int idx = tid; idx < 8192; idx += 128) {
        int j = idx >> 7, k = idx & 127;
        pool[W1S_OFF + k * 64 + j] = W1[idx];
    }
    __syncthreads();

#pragma unroll
    for (int ii = 0; ii < 4; ii++) {
        int idx = tid + 128 * ii;
        int r = idx >> 6, j = idx & 63;
        float a = b1[j];
#pragma unroll 8
        for (int k = 0; k < 128; k++)
            a += pool[W1S_OFF + k * 64 + j] * pool[HS_OFF + r * 128 + k];
        pool[H1_OFF + r * 64 + j] = (a > 0.f) ? a : 0.01f * a;
    }
    __syncthreads();

    for (int idx = tid; idx < 2048; idx += 128) {
        int j = idx >> 6, k = idx & 63;
        pool[W2S_OFF + k * 32 + j] = W2[idx];
    }
    for (int idx = tid; idx < 256; idx += 128) {
        int j = idx >> 5, k = idx & 31;
        pool[W3S_OFF + k * 8 + j] = W3[idx];
    }
    __syncthreads();

#pragma unroll
    for (int ii = 0; ii < 2; ii++) {
        int idx = tid + 128 * ii;
        int r = idx >> 5, j = idx & 31;
        float a = b2[j];
#pragma unroll 8
        for (int k = 0; k < 64; k++)
            a += pool[W2S_OFF + k * 32 + j] * pool[H1_OFF + r * 64 + k];
        pool[H2_OFF + r * 32 + j] = (a > 0.f) ? a : 0.01f * a;
    }
    __syncthreads();

    if (tid < 64) {
        int r = tid >> 3, j = tid & 7;
        float a = b3[j];
#pragma unroll
        for (int k = 0; k < 32; k++)
            a += pool[W3S_OFF + k * 8 + j] * pool[H2_OFF + r * 32 + k];
        pool[H1_OFF + r * 8 + j] = (a > 0.f) ? a : 0.01f * a;
    }
    __syncthreads();

    if (tid < 8) {
        int r = tid;
        float vv[8];
        float m = -1e30f;
#pragma unroll
        for (int c = 0; c < 8; c++) {
            vv[c] = pool[H1_OFF + r * 8 + c];
            m = fmaxf(m, vv[c]);
        }
        float s = 0.f;
#pragma unroll
        for (int c = 0; c < 8; c++) { vv[c] = expf(vv[c] - m); s += vv[c]; }
        float inv = 1.0f / s;
#pragma unroll
        for (int c = 0; c < 8; c++) out[(row0 + r) * 8 + c] = vv[c] * inv;
    }
}

// ---------------- launch ----------------
extern "C" void kernel_launch(void* const* d_in, const int* in_sizes, int n_in,
                              void* d_out, int out_size) {
    const float* x   = (const float*)d_in[0];
    const float* adj = (const float*)d_in[1];
    const float* Wp  = (const float*)d_in[2];
    const float* W1  = (const float*)d_in[3];
    const float* b1  = (const float*)d_in[4];
    const float* W2  = (const float*)d_in[5];
    const float* b2  = (const float*)d_in[6];
    const float* W3  = (const float*)d_in[7];
    const float* b3  = (const float*)d_in[8];
    float* out = (float*)d_out;

    const int smem_bytes = (2 * A_STAGE + 3 * B_STAGE) * 4;   // 81920
    cudaFuncSetAttribute(gemm_h, cudaFuncAttributeMaxDynamicSharedMemorySize, smem_bytes);

    dim3 gridT(NROWS / 32, NFEATD / 32);
    transpose_x<<<gridT, dim3(32, 8)>>>(x);

    gemm_h<<<NROWS / BMh, 512, smem_bytes>>>(adj);

    mlp_kernel<<<NROWS / 8, 128>>>(x, Wp, W1, b1, W2, b2, W3, b3, out);
}

// round 6
// speedup vs baseline: 11.1531x; 1.7983x over previous
#include <cuda_runtime.h>
#include <cuda_fp16.h>
#include <cstdint>

#define NROWS 16384
#define NF    256

// ---------------- scratch (no allocations allowed) ----------------
__device__ __half g_xcat[NROWS * 768];     // [x_hi | x_hi | x_lo] per row
__device__ __half g_wcat[128 * 768];       // [w1_hi | w1_lo | w1_hi] per out
__device__ __half g_wp2h[128 * 256];       // Wp[:,256:512] fp16
__device__ __half g_yTh[128 * NROWS];      // yT = Wp2h @ x^T  [128][16384]
__device__ float  g_xp[NROWS * 128];       // x @ Wp1^T (split-fp16 accurate)

// ---------------- helpers ----------------
__device__ __forceinline__ void cp16(uint32_t saddr, const void* gaddr) {
    asm volatile("cp.async.cg.shared.global [%0], [%1], 16;"
                 :: "r"(saddr), "l"(gaddr));
}
__device__ __forceinline__ uint32_t cvta_smem(const void* p) {
    uint32_t a;
    asm("{ .reg .u64 t; cvta.to.shared.u64 t, %1; cvt.u32.u64 %0, t; }"
        : "=r"(a) : "l"(p));
    return a;
}
__device__ __forceinline__ void mma_f16(float& d0, float& d1, float& d2, float& d3,
                                        uint32_t a0, uint32_t a1, uint32_t a2, uint32_t a3,
                                        uint32_t b0, uint32_t b1) {
    asm volatile(
        "mma.sync.aligned.m16n8k16.row.col.f32.f16.f16.f32 "
        "{%0,%1,%2,%3}, {%4,%5,%6,%7}, {%8,%9}, {%0,%1,%2,%3};"
        : "+f"(d0), "+f"(d1), "+f"(d2), "+f"(d3)
        : "r"(a0), "r"(a1), "r"(a2), "r"(a3), "r"(b0), "r"(b1));
}
__device__ __forceinline__ uint32_t h2u(__half2 h) {
    return *reinterpret_cast<uint32_t*>(&h);
}

// ================= P1: conversions =================
__global__ __launch_bounds__(256)
void convert_x(const float* __restrict__ x) {
    int idx = blockIdx.x * 256 + threadIdx.x;   // 1,048,576 total
    int row = idx >> 6;
    int c   = (idx & 63) * 4;
    float4 v = *reinterpret_cast<const float4*>(x + (size_t)row * NF + c);
    __half hx = __float2half_rn(v.x), hy = __float2half_rn(v.y);
    __half hz = __float2half_rn(v.z), hw = __float2half_rn(v.w);
    __half lx = __float2half_rn(v.x - __half2float(hx));
    __half ly = __float2half_rn(v.y - __half2float(hy));
    __half lz = __float2half_rn(v.z - __half2float(hz));
    __half lw = __float2half_rn(v.w - __half2float(hw));
    __half2* base = reinterpret_cast<__half2*>(g_xcat + (size_t)row * 768);
    __half2 h01; h01.x = hx; h01.y = hy;
    __half2 h23; h23.x = hz; h23.y = hw;
    __half2 l01; l01.x = lx; l01.y = ly;
    __half2 l23; l23.x = lz; l23.y = lw;
    base[c / 2]             = h01;  base[c / 2 + 1]             = h23;
    base[(256 + c) / 2]     = h01;  base[(256 + c) / 2 + 1]     = h23;
    base[(512 + c) / 2]     = l01;  base[(512 + c) / 2 + 1]     = l23;
}

__global__ __launch_bounds__(256)
void convert_w(const float* __restrict__ Wp) {
    int idx = blockIdx.x * 256 + threadIdx.x;   // 65536 total
    int n = idx >> 9, c = idx & 511;
    float v = Wp[idx];
    __half h = __float2half_rn(v);
    if (c < 256) {
        __half l = __float2half_rn(v - __half2float(h));
        g_wcat[n * 768 + c]       = h;
        g_wcat[n * 768 + 256 + c] = l;
        g_wcat[n * 768 + 512 + c] = h;
    } else {
        g_wp2h[n * 256 + (c - 256)] = h;
    }
}

// ================= P2: yT = Wp2h @ x^T  (C [128][16384] fp16) =========
// grid 128 CTAs (128 node-cols each), 256 threads, 8 warps: 2M x 4N, warp 64x32.
#define P_AST 2560           // 128 rows * 20 u32
__device__ __forceinline__ void p_load(uint32_t dst, const __half* src,
                                       int pitch, int k0, int tid) {
#pragma unroll
    for (int j = 0; j < 2; j++) {
        int q = tid + 256 * j;
        int r = q >> 2, cc = q & 3;
        cp16(dst + r * 80 + cc * 16, src + (size_t)r * pitch + k0 + cc * 8);
    }
}

__global__ __launch_bounds__(256)
void p2_yT() {
    extern __shared__ uint32_t sm2[];
    const int tid = threadIdx.x, wid = tid >> 5, lane = tid & 31;
    const int lq = lane >> 2, lr = lane & 3;
    const int wm = wid & 1, wn = wid >> 1;
    const int n0 = blockIdx.x * 128;
    uint32_t abase = cvta_smem(sm2);
    uint32_t bbase = abase + 2 * P_AST * 4;

    float acc[4][4][4];
#pragma unroll
    for (int i = 0; i < 4; i++)
#pragma unroll
        for (int j = 0; j < 4; j++)
#pragma unroll
            for (int v = 0; v < 4; v++) acc[i][j][v] = 0.f;

#pragma unroll
    for (int s = 0; s < 2; s++) {
        p_load(abase + s * P_AST * 4, g_wp2h, 256, s * 32, tid);
        p_load(bbase + s * P_AST * 4, g_xcat + (size_t)n0 * 768, 768, s * 32, tid);
        asm volatile("cp.async.commit_group;" ::: "memory");
    }
    const int NI = 8;
#pragma unroll 1
    for (int i = 0; i < NI; i++) {
        int s = i & 1;
        if (i < NI - 1) asm volatile("cp.async.wait_group 1;" ::: "memory");
        else            asm volatile("cp.async.wait_group 0;" ::: "memory");
        __syncthreads();
        const uint32_t* As = sm2 + s * P_AST;
        const uint32_t* Bs = sm2 + 2 * P_AST + s * P_AST;
#pragma unroll
        for (int ks = 0; ks < 2; ks++) {
            uint32_t af[4][4];
#pragma unroll
            for (int mt = 0; mt < 4; mt++) {
                int b = (wm * 64 + mt * 16 + lq) * 20 + ks * 8 + lr;
                af[mt][0] = As[b]; af[mt][1] = As[b + 160];
                af[mt][2] = As[b + 4]; af[mt][3] = As[b + 164];
            }
            uint32_t bf[4][2];
#pragma unroll
            for (int nt = 0; nt < 4; nt++) {
                int b = (wn * 32 + nt * 8 + lq) * 20 + ks * 8 + lr;
                bf[nt][0] = Bs[b]; bf[nt][1] = Bs[b + 4];
            }
#pragma unroll
            for (int mt = 0; mt < 4; mt++)
#pragma unroll
                for (int nt = 0; nt < 4; nt++)
                    mma_f16(acc[mt][nt][0], acc[mt][nt][1], acc[mt][nt][2], acc[mt][nt][3],
                            af[mt][0], af[mt][1], af[mt][2], af[mt][3],
                            bf[nt][0], bf[nt][1]);
        }
        __syncthreads();
        if (i + 2 < NI) {
            p_load(abase + s * P_AST * 4, g_wp2h, 256, (i + 2) * 32, tid);
            p_load(bbase + s * P_AST * 4, g_xcat + (size_t)n0 * 768, 768, (i + 2) * 32, tid);
            asm volatile("cp.async.commit_group;" ::: "memory");
        }
    }
#pragma unroll
    for (int mt = 0; mt < 4; mt++)
#pragma unroll
        for (int nt = 0; nt < 4; nt++) {
            int r = wm * 64 + mt * 16 + lq;
            int n = n0 + wn * 32 + nt * 8 + lr * 2;
            __half2 v0; v0.x = __float2half_rn(acc[mt][nt][0]); v0.y = __float2half_rn(acc[mt][nt][1]);
            __half2 v1; v1.x = __float2half_rn(acc[mt][nt][2]); v1.y = __float2half_rn(acc[mt][nt][3]);
            *reinterpret_cast<__half2*>(g_yTh + (size_t)r * NROWS + n) = v0;
            *reinterpret_cast<__half2*>(g_yTh + (size_t)(r + 8) * NROWS + n) = v1;
        }
}

// ================= P3: xp = xcat @ wcat^T  (C [16384][128] fp32) =======
// grid 128 CTAs (128 rows each), 256 threads, 8 warps: 4M x 2N, warp 32x64.
__global__ __launch_bounds__(256)
void p3_xp() {
    extern __shared__ uint32_t sm3[];
    const int tid = threadIdx.x, wid = tid >> 5, lane = tid & 31;
    const int lq = lane >> 2, lr = lane & 3;
    const int wm = wid & 3, wn = wid >> 2;
    const int m0 = blockIdx.x * 128;
    uint32_t abase = cvta_smem(sm3);
    uint32_t bbase = abase + 2 * P_AST * 4;

    float acc[2][8][4];
#pragma unroll
    for (int i = 0; i < 2; i++)
#pragma unroll
        for (int j = 0; j < 8; j++)
#pragma unroll
            for (int v = 0; v < 4; v++) acc[i][j][v] = 0.f;

#pragma unroll
    for (int s = 0; s < 2; s++) {
        p_load(abase + s * P_AST * 4, g_xcat + (size_t)m0 * 768, 768, s * 32, tid);
        p_load(bbase + s * P_AST * 4, g_wcat, 768, s * 32, tid);
        asm volatile("cp.async.commit_group;" ::: "memory");
    }
    const int NI = 24;
#pragma unroll 1
    for (int i = 0; i < NI; i++) {
        int s = i & 1;
        if (i < NI - 1) asm volatile("cp.async.wait_group 1;" ::: "memory");
        else            asm volatile("cp.async.wait_group 0;" ::: "memory");
        __syncthreads();
        const uint32_t* As = sm3 + s * P_AST;
        const uint32_t* Bs = sm3 + 2 * P_AST + s * P_AST;
#pragma unroll
        for (int ks = 0; ks < 2; ks++) {
            uint32_t af[2][4];
#pragma unroll
            for (int mt = 0; mt < 2; mt++) {
                int b = (wm * 32 + mt * 16 + lq) * 20 + ks * 8 + lr;
                af[mt][0] = As[b]; af[mt][1] = As[b + 160];
                af[mt][2] = As[b + 4]; af[mt][3] = As[b + 164];
            }
            uint32_t bf[8][2];
#pragma unroll
            for (int nt = 0; nt < 8; nt++) {
                int b = (wn * 64 + nt * 8 + lq) * 20 + ks * 8 + lr;
                bf[nt][0] = Bs[b]; bf[nt][1] = Bs[b + 4];
            }
#pragma unroll
            for (int mt = 0; mt < 2; mt++)
#pragma unroll
                for (int nt = 0; nt < 8; nt++)
                    mma_f16(acc[mt][nt][0], acc[mt][nt][1], acc[mt][nt][2], acc[mt][nt][3],
                            af[mt][0], af[mt][1], af[mt][2], af[mt][3],
                            bf[nt][0], bf[nt][1]);
        }
        __syncthreads();
        if (i + 2 < NI) {
            p_load(abase + s * P_AST * 4, g_xcat + (size_t)m0 * 768, 768, (i + 2) * 32, tid);
            p_load(bbase + s * P_AST * 4, g_wcat, 768, (i + 2) * 32, tid);
            asm volatile("cp.async.commit_group;" ::: "memory");
        }
    }
#pragma unroll
    for (int mt = 0; mt < 2; mt++)
#pragma unroll
        for (int nt = 0; nt < 8; nt++) {
            int r = m0 + wm * 32 + mt * 16 + lq;
            int c = wn * 64 + nt * 8 + lr * 2;
            *reinterpret_cast<float2*>(g_xp + (size_t)r * 128 + c) =
                make_float2(acc[mt][nt][0], acc[mt][nt][1]);
            *reinterpret_cast<float2*>(g_xp + (size_t)(r + 8) * 128 + c) =
                make_float2(acc[mt][nt][2], acc[mt][nt][3]);
        }
}

// ================= Kernel Z: z = adj @ y, fused h/MLP/softmax epilogue ====
#define ZA_ST 2560            // 128 rows * 20 u32 (fp16 A stage)
#define ZB_ST 2560            // 128 n-rows * 20 u32
#define NIZ   512
// epilogue smem offsets (floats)
#define H_OFF   0             // 128 x 132
#define H1_OFF  16896         // 128 x 68
#define W1T_OFF 25600         // 128 x 64
#define H2_OFF  33792         // 128 x 36
#define W2T_OFF 38400         // 64 x 32
#define W3T_OFF 40448         // 32 x 8
#define LG_OFF  40704         // 128 x 8
#define DEG_OFF 41728         // 128
#define Z_SMEM_FLOATS 41856

__global__ __launch_bounds__(512, 1)
void gemm_z(const float* __restrict__ adj,
            const float* __restrict__ W1, const float* __restrict__ b1,
            const float* __restrict__ W2, const float* __restrict__ b2,
            const float* __restrict__ W3, const float* __restrict__ b3,
            float* __restrict__ out) {
    extern __shared__ uint32_t smz[];
    uint32_t* Abuf = smz;
    uint32_t* Bbuf = smz + 2 * ZA_ST;
    float* pool = reinterpret_cast<float*>(smz);

    const int tid = threadIdx.x, wid = tid >> 5, lane = tid & 31;
    const int lq = lane >> 2, lr = lane & 3;
    const int gg = lane >> 3, cc = lane & 7;
    const int wm = wid & 3, wn = wid >> 2;      // 4M x 4N warps, tile 32x32
    const int m0 = blockIdx.x * 128;
    const uint32_t bbase = cvta_smem(Bbuf);

    float acc[2][4][4];
#pragma unroll
    for (int i = 0; i < 2; i++)
#pragma unroll
        for (int j = 0; j < 4; j++)
#pragma unroll
            for (int v = 0; v < 4; v++) acc[i][j][v] = 0.f;

    // B prologue (3 stages)
#pragma unroll
    for (int s = 0; s < 3; s++) {
        int n = tid >> 2, c4 = tid & 3;
        cp16(bbase + s * (ZB_ST * 4) + n * 80 + c4 * 16,
             g_yTh + (size_t)n * NROWS + s * 32 + c4 * 8);
        asm volatile("cp.async.commit_group;" ::: "memory");
    }

    const int rowA0 = wid * 8 + gg;
    float4 areg[2];
#pragma unroll
    for (int p = 0; p < 2; p++)
        areg[p] = *reinterpret_cast<const float4*>(
            adj + (size_t)(m0 + rowA0 + p * 4) * NROWS + cc * 4);
    float degp[2] = {0.f, 0.f};

#pragma unroll 1
    for (int i = 0; i < NIZ; i++) {
        const int sA = i & 1;
        const int sB = i % 3;
#pragma unroll
        for (int p = 0; p < 2; p++) {
            float4 v = areg[p];
            degp[p] += (v.x + v.y) + (v.z + v.w);
            __half2 h0 = __floats2half2_rn(v.x, v.y);
            __half2 h1 = __floats2half2_rn(v.z, v.w);
            uint32_t* dst = Abuf + sA * ZA_ST + (rowA0 + p * 4) * 20 + cc * 2;
            dst[0] = h2u(h0);
            dst[1] = h2u(h1);
        }
        if (i + 1 < NIZ) {
            int k0n = (i + 1) * 32;
#pragma unroll
            for (int p = 0; p < 2; p++)
                areg[p] = *reinterpret_cast<const float4*>(
                    adj + (size_t)(m0 + rowA0 + p * 4) * NROWS + k0n + cc * 4);
        }
        int rem = (NIZ - 1) - i;
        if (rem >= 2)      asm volatile("cp.async.wait_group 2;" ::: "memory");
        else if (rem == 1) asm volatile("cp.async.wait_group 1;" ::: "memory");
        else               asm volatile("cp.async.wait_group 0;" ::: "memory");
        __syncthreads();

        const uint32_t* As = Abuf + sA * ZA_ST;
        const uint32_t* Bs = Bbuf + sB * ZB_ST;
#pragma unroll
        for (int ks = 0; ks < 2; ks++) {
            uint32_t af[2][4];
#pragma unroll
            for (int mt = 0; mt < 2; mt++) {
                int b = (wm * 32 + mt * 16 + lq) * 20 + ks * 8 + lr;
                af[mt][0] = As[b]; af[mt][1] = As[b + 160];
                af[mt][2] = As[b + 4]; af[mt][3] = As[b + 164];
            }
            uint32_t bf[4][2];
#pragma unroll
            for (int nt = 0; nt < 4; nt++) {
                int b = (wn * 32 + nt * 8 + lq) * 20 + ks * 8 + lr;
                bf[nt][0] = Bs[b]; bf[nt][1] = Bs[b + 4];
            }
#pragma unroll
            for (int mt = 0; mt < 2; mt++)
#pragma unroll
                for (int nt = 0; nt < 4; nt++)
                    mma_f16(acc[mt][nt][0], acc[mt][nt][1], acc[mt][nt][2], acc[mt][nt][3],
                            af[mt][0], af[mt][1], af[mt][2], af[mt][3],
                            bf[nt][0], bf[nt][1]);
        }
        __syncthreads();
        if (i + 3 < NIZ) {
            int sN = (i + 3) % 3;
            int n = tid >> 2, c4 = tid & 3;
            cp16(bbase + sN * (ZB_ST * 4) + n * 80 + c4 * 16,
                 g_yTh + (size_t)n * NROWS + (i + 3) * 32 + c4 * 8);
            asm volatile("cp.async.commit_group;" ::: "memory");
        }
    }

    // ---- deg to smem ----
#pragma unroll
    for (int p = 0; p < 2; p++) {
        float d = degp[p];
#pragma unroll
        for (int off = 1; off < 8; off <<= 1)
            d += __shfl_xor_sync(0xffffffffu, d, off);
        if (cc == 0) pool[DEG_OFF + rowA0 + p * 4] = d + 1.0f;
    }
    __syncthreads();

    // ---- h = relu(xp + z/deg) -> smem ----
#pragma unroll
    for (int mt = 0; mt < 2; mt++) {
        int r = wm * 32 + mt * 16 + lq;
        float inv0 = 1.0f / pool[DEG_OFF + r];
        float inv1 = 1.0f / pool[DEG_OFF + r + 8];
#pragma unroll
        for (int nt = 0; nt < 4; nt++) {
            int c = wn * 32 + nt * 8 + lr * 2;
            float2 x0 = *reinterpret_cast<const float2*>(g_xp + (size_t)(m0 + r) * 128 + c);
            float2 x1 = *reinterpret_cast<const float2*>(g_xp + (size_t)(m0 + r + 8) * 128 + c);
            pool[H_OFF + r * 132 + c]           = fmaxf(x0.x + acc[mt][nt][0] * inv0, 0.f);
            pool[H_OFF + r * 132 + c + 1]       = fmaxf(x0.y + acc[mt][nt][1] * inv0, 0.f);
            pool[H_OFF + (r + 8) * 132 + c]     = fmaxf(x1.x + acc[mt][nt][2] * inv1, 0.f);
            pool[H_OFF + (r + 8) * 132 + c + 1] = fmaxf(x1.y + acc[mt][nt][3] * inv1, 0.f);
        }
    }
    // stage W1T/W2T/W3T
    for (int idx = tid; idx < 8192; idx += 512) {
        int j = idx >> 7, k = idx & 127;
        pool[W1T_OFF + k * 64 + j] = W1[idx];
    }
    for (int idx = tid; idx < 2048; idx += 512) {
        int j = idx >> 6, k = idx & 63;
        pool[W2T_OFF + k * 32 + j] = W2[idx];
    }
    if (tid < 256) {
        int j = tid >> 5, k = tid & 31;
        pool[W3T_OFF + k * 8 + j] = W3[tid];
    }
    __syncthreads();

    // ---- MLP1: h1 = lrelu(h @ W1^T + b1)  (128x64) ----
    {
        const int jg = tid & 15, rg = tid >> 4;    // 4 j x 4 r per thread
        float a[4][4];
#pragma unroll
        for (int jj = 0; jj < 4; jj++) {
            float bb = b1[jg * 4 + jj];
#pragma unroll
            for (int ri = 0; ri < 4; ri++) a[ri][jj] = bb;
        }
#pragma unroll 4
        for (int k = 0; k < 128; k++) {
            float4 wv = *reinterpret_cast<const float4*>(&pool[W1T_OFF + k * 64 + jg * 4]);
#pragma unroll
            for (int ri = 0; ri < 4; ri++) {
                float hv = pool[H_OFF + (rg * 4 + ri) * 132 + k];
                a[ri][0] += hv * wv.x; a[ri][1] += hv * wv.y;
                a[ri][2] += hv * wv.z; a[ri][3] += hv * wv.w;
            }
        }
#pragma unroll
        for (int ri = 0; ri < 4; ri++)
#pragma unroll
            for (int jj = 0; jj < 4; jj++) {
                float v = a[ri][jj];
                pool[H1_OFF + (rg * 4 + ri) * 68 + jg * 4 + jj] = (v > 0.f) ? v : 0.01f * v;
            }
    }
    __syncthreads();

    // ---- MLP2: h2 = lrelu(h1 @ W2^T + b2) (128x32) ----
#pragma unroll
    for (int ii = 0; ii < 8; ii++) {
        int o = tid + 512 * ii;
        int r = o >> 5, j = o & 31;
        float a = b2[j];
#pragma unroll 8
        for (int k = 0; k < 64; k++)
            a += pool[H1_OFF + r * 68 + k] * pool[W2T_OFF + k * 32 + j];
        pool[H2_OFF + r * 36 + j] = (a > 0.f) ? a : 0.01f * a;
    }
    __syncthreads();

    // ---- MLP3: logits (128x8) ----
#pragma unroll
    for (int ii = 0; ii < 2; ii++) {
        int o = tid + 512 * ii;
        int r = o >> 3, j = o & 7;
        float a = b3[j];
#pragma unroll
        for (int k = 0; k < 32; k++)
            a += pool[H2_OFF + r * 36 + k] * pool[W3T_OFF + k * 8 + j];
        pool[LG_OFF + r * 8 + j] = (a > 0.f) ? a : 0.01f * a;
    }
    __syncthreads();

    // ---- softmax + write ----
    if (tid < 128) {
        int r = tid;
        float vv[8], m = -1e30f;
#pragma unroll
        for (int c = 0; c < 8; c++) {
            vv[c] = pool[LG_OFF + r * 8 + c];
            m = fmaxf(m, vv[c]);
        }
        float s = 0.f;
#pragma unroll
        for (int c = 0; c < 8; c++) { vv[c] = expf(vv[c] - m); s += vv[c]; }
        float inv = 1.0f / s;
        float4 o0 = make_float4(vv[0] * inv, vv[1] * inv, vv[2] * inv, vv[3] * inv);
        float4 o1 = make_float4(vv[4] * inv, vv[5] * inv, vv[6] * inv, vv[7] * inv);
        *reinterpret_cast<float4*>(out + (size_t)(m0 + r) * 8)     = o0;
        *reinterpret_cast<float4*>(out + (size_t)(m0 + r) * 8 + 4) = o1;
    }
}

// ---------------- launch ----------------
extern "C" void kernel_launch(void* const* d_in, const int* in_sizes, int n_in,
                              void* d_out, int out_size) {
    const float* x   = (const float*)d_in[0];
    const float* adj = (const float*)d_in[1];
    const float* Wp  = (const float*)d_in[2];
    const float* W1  = (const float*)d_in[3];
    const float* b1  = (const float*)d_in[4];
    const float* W2  = (const float*)d_in[5];
    const float* b2  = (const float*)d_in[6];
    const float* W3  = (const float*)d_in[7];
    const float* b3  = (const float*)d_in[8];
    float* out = (float*)d_out;

    const int psm = 4 * P_AST * 4;                  // 40960
    const int zsm = Z_SMEM_FLOATS * 4;              // 167424
    cudaFuncSetAttribute(p2_yT, cudaFuncAttributeMaxDynamicSharedMemorySize, psm);
    cudaFuncSetAttribute(p3_xp, cudaFuncAttributeMaxDynamicSharedMemorySize, psm);
    cudaFuncSetAttribute(gemm_z, cudaFuncAttributeMaxDynamicSharedMemorySize, zsm);

    convert_x<<<4096, 256>>>(x);
    convert_w<<<256, 256>>>(Wp);
    p2_yT<<<128, 256, psm>>>();
    p3_xp<<<128, 256, psm>>>();
    gemm_z<<<128, 512, zsm>>>(adj, W1, b1, W2, b2, W3, b3, out);
}

// round 7
// speedup vs baseline: 11.1767x; 1.0021x over previous
#include <cuda_runtime.h>
#include <cuda_fp16.h>
#include <cstdint>

#define NROWS 16384
#define NF    256

// ---------------- scratch (no allocations allowed) ----------------
__device__ __half g_xcat[NROWS * 768];     // [x_hi | x_hi | x_lo] per row
__device__ __half g_wcat[128 * 768];       // [w1_hi | w1_lo | w1_hi] per out
__device__ __half g_wp2h[128 * 256];       // Wp[:,256:512] fp16
__device__ __half g_yTh[128 * NROWS];      // yT = Wp2h @ x^T  [128][16384]
__device__ float  g_xp[NROWS * 128];       // x @ Wp1^T (split-fp16 accurate)

// ---------------- helpers ----------------
__device__ __forceinline__ void cp16(uint32_t saddr, const void* gaddr) {
    asm volatile("cp.async.cg.shared.global [%0], [%1], 16;"
                 :: "r"(saddr), "l"(gaddr));
}
__device__ __forceinline__ uint32_t cvta_smem(const void* p) {
    uint32_t a;
    asm("{ .reg .u64 t; cvta.to.shared.u64 t, %1; cvt.u32.u64 %0, t; }"
        : "=r"(a) : "l"(p));
    return a;
}
__device__ __forceinline__ void mma_f16(float& d0, float& d1, float& d2, float& d3,
                                        uint32_t a0, uint32_t a1, uint32_t a2, uint32_t a3,
                                        uint32_t b0, uint32_t b1) {
    asm volatile(
        "mma.sync.aligned.m16n8k16.row.col.f32.f16.f16.f32 "
        "{%0,%1,%2,%3}, {%4,%5,%6,%7}, {%8,%9}, {%0,%1,%2,%3};"
        : "+f"(d0), "+f"(d1), "+f"(d2), "+f"(d3)
        : "r"(a0), "r"(a1), "r"(a2), "r"(a3), "r"(b0), "r"(b1));
}
__device__ __forceinline__ uint32_t h2u(__half2 h) {
    return *reinterpret_cast<uint32_t*>(&h);
}

// ================= P1: conversions =================
__global__ __launch_bounds__(256)
void convert_x(const float* __restrict__ x) {
    int idx = blockIdx.x * 256 + threadIdx.x;   // 1,048,576 total
    int row = idx >> 6;
    int c   = (idx & 63) * 4;
    float4 v = *reinterpret_cast<const float4*>(x + (size_t)row * NF + c);
    __half hx = __float2half_rn(v.x), hy = __float2half_rn(v.y);
    __half hz = __float2half_rn(v.z), hw = __float2half_rn(v.w);
    __half lx = __float2half_rn(v.x - __half2float(hx));
    __half ly = __float2half_rn(v.y - __half2float(hy));
    __half lz = __float2half_rn(v.z - __half2float(hz));
    __half lw = __float2half_rn(v.w - __half2float(hw));
    __half2* base = reinterpret_cast<__half2*>(g_xcat + (size_t)row * 768);
    __half2 h01; h01.x = hx; h01.y = hy;
    __half2 h23; h23.x = hz; h23.y = hw;
    __half2 l01; l01.x = lx; l01.y = ly;
    __half2 l23; l23.x = lz; l23.y = lw;
    base[c / 2]             = h01;  base[c / 2 + 1]             = h23;
    base[(256 + c) / 2]     = h01;  base[(256 + c) / 2 + 1]     = h23;
    base[(512 + c) / 2]     = l01;  base[(512 + c) / 2 + 1]     = l23;
}

__global__ __launch_bounds__(256)
void convert_w(const float* __restrict__ Wp) {
    int idx = blockIdx.x * 256 + threadIdx.x;   // 65536 total
    int n = idx >> 9, c = idx & 511;
    float v = Wp[idx];
    __half h = __float2half_rn(v);
    if (c < 256) {
        __half l = __float2half_rn(v - __half2float(h));
        g_wcat[n * 768 + c]       = h;
        g_wcat[n * 768 + 256 + c] = l;
        g_wcat[n * 768 + 512 + c] = h;
    } else {
        g_wp2h[n * 256 + (c - 256)] = h;
    }
}

// ================= P2: yT = Wp2h @ x^T  (C [128][16384] fp16) =========
// grid 128 CTAs (128 node-cols each), 256 threads, 8 warps: 2M x 4N, warp 64x32.
#define P_AST 2560           // 128 rows * 20 u32
__device__ __forceinline__ void p_load(uint32_t dst, const __half* src,
                                       int pitch, int k0, int tid) {
#pragma unroll
    for (int j = 0; j < 2; j++) {
        int q = tid + 256 * j;
        int r = q >> 2, cc = q & 3;
        cp16(dst + r * 80 + cc * 16, src + (size_t)r * pitch + k0 + cc * 8);
    }
}

__global__ __launch_bounds__(256)
void p2_yT() {
    extern __shared__ uint32_t sm2[];
    const int tid = threadIdx.x, wid = tid >> 5, lane = tid & 31;
    const int lq = lane >> 2, lr = lane & 3;
    const int wm = wid & 1, wn = wid >> 1;
    const int n0 = blockIdx.x * 128;
    uint32_t abase = cvta_smem(sm2);
    uint32_t bbase = abase + 2 * P_AST * 4;

    float acc[4][4][4];
#pragma unroll
    for (int i = 0; i < 4; i++)
#pragma unroll
        for (int j = 0; j < 4; j++)
#pragma unroll
            for (int v = 0; v < 4; v++) acc[i][j][v] = 0.f;

#pragma unroll
    for (int s = 0; s < 2; s++) {
        p_load(abase + s * P_AST * 4, g_wp2h, 256, s * 32, tid);
        p_load(bbase + s * P_AST * 4, g_xcat + (size_t)n0 * 768, 768, s * 32, tid);
        asm volatile("cp.async.commit_group;" ::: "memory");
    }
    const int NI = 8;
#pragma unroll 1
    for (int i = 0; i < NI; i++) {
        int s = i & 1;
        if (i < NI - 1) asm volatile("cp.async.wait_group 1;" ::: "memory");
        else            asm volatile("cp.async.wait_group 0;" ::: "memory");
        __syncthreads();
        const uint32_t* As = sm2 + s * P_AST;
        const uint32_t* Bs = sm2 + 2 * P_AST + s * P_AST;
#pragma unroll
        for (int ks = 0; ks < 2; ks++) {
            uint32_t af[4][4];
#pragma unroll
            for (int mt = 0; mt < 4; mt++) {
                int b = (wm * 64 + mt * 16 + lq) * 20 + ks * 8 + lr;
                af[mt][0] = As[b]; af[mt][1] = As[b + 160];
                af[mt][2] = As[b + 4]; af[mt][3] = As[b + 164];
            }
            uint32_t bf[4][2];
#pragma unroll
            for (int nt = 0; nt < 4; nt++) {
                int b = (wn * 32 + nt * 8 + lq) * 20 + ks * 8 + lr;
                bf[nt][0] = Bs[b]; bf[nt][1] = Bs[b + 4];
            }
#pragma unroll
            for (int mt = 0; mt < 4; mt++)
#pragma unroll
                for (int nt = 0; nt < 4; nt++)
                    mma_f16(acc[mt][nt][0], acc[mt][nt][1], acc[mt][nt][2], acc[mt][nt][3],
                            af[mt][0], af[mt][1], af[mt][2], af[mt][3],
                            bf[nt][0], bf[nt][1]);
        }
        __syncthreads();
        if (i + 2 < NI) {
            p_load(abase + s * P_AST * 4, g_wp2h, 256, (i + 2) * 32, tid);
            p_load(bbase + s * P_AST * 4, g_xcat + (size_t)n0 * 768, 768, (i + 2) * 32, tid);
            asm volatile("cp.async.commit_group;" ::: "memory");
        }
    }
#pragma unroll
    for (int mt = 0; mt < 4; mt++)
#pragma unroll
        for (int nt = 0; nt < 4; nt++) {
            int r = wm * 64 + mt * 16 + lq;
            int n = n0 + wn * 32 + nt * 8 + lr * 2;
            __half2 v0; v0.x = __float2half_rn(acc[mt][nt][0]); v0.y = __float2half_rn(acc[mt][nt][1]);
            __half2 v1; v1.x = __float2half_rn(acc[mt][nt][2]); v1.y = __float2half_rn(acc[mt][nt][3]);
            *reinterpret_cast<__half2*>(g_yTh + (size_t)r * NROWS + n) = v0;
            *reinterpret_cast<__half2*>(g_yTh + (size_t)(r + 8) * NROWS + n) = v1;
        }
}

// ================= P3: xp = xcat @ wcat^T  (C [16384][128] fp32) =======
// grid 128 CTAs (128 rows each), 256 threads, 8 warps: 4M x 2N, warp 32x64.
__global__ __launch_bounds__(256)
void p3_xp() {
    extern __shared__ uint32_t sm3[];
    const int tid = threadIdx.x, wid = tid >> 5, lane = tid & 31;
    const int lq = lane >> 2, lr = lane & 3;
    const int wm = wid & 3, wn = wid >> 2;
    const int m0 = blockIdx.x * 128;
    uint32_t abase = cvta_smem(sm3);
    uint32_t bbase = abase + 2 * P_AST * 4;

    float acc[2][8][4];
#pragma unroll
    for (int i = 0; i < 2; i++)
#pragma unroll
        for (int j = 0; j < 8; j++)
#pragma unroll
            for (int v = 0; v < 4; v++) acc[i][j][v] = 0.f;

#pragma unroll
    for (int s = 0; s < 2; s++) {
        p_load(abase + s * P_AST * 4, g_xcat + (size_t)m0 * 768, 768, s * 32, tid);
        p_load(bbase + s * P_AST * 4, g_wcat, 768, s * 32, tid);
        asm volatile("cp.async.commit_group;" ::: "memory");
    }
    const int NI = 24;
#pragma unroll 1
    for (int i = 0; i < NI; i++) {
        int s = i & 1;
        if (i < NI - 1) asm volatile("cp.async.wait_group 1;" ::: "memory");
        else            asm volatile("cp.async.wait_group 0;" ::: "memory");
        __syncthreads();
        const uint32_t* As = sm3 + s * P_AST;
        const uint32_t* Bs = sm3 + 2 * P_AST + s * P_AST;
#pragma unroll
        for (int ks = 0; ks < 2; ks++) {
            uint32_t af[2][4];
#pragma unroll
            for (int mt = 0; mt < 2; mt++) {
                int b = (wm * 32 + mt * 16 + lq) * 20 + ks * 8 + lr;
                af[mt][0] = As[b]; af[mt][1] = As[b + 160];
                af[mt][2] = As[b + 4]; af[mt][3] = As[b + 164];
            }
            uint32_t bf[8][2];
#pragma unroll
            for (int nt = 0; nt < 8; nt++) {
                int b = (wn * 64 + nt * 8 + lq) * 20 + ks * 8 + lr;
                bf[nt][0] = Bs[b]; bf[nt][1] = Bs[b + 4];
            }
#pragma unroll
            for (int mt = 0; mt < 2; mt++)
#pragma unroll
                for (int nt = 0; nt < 8; nt++)
                    mma_f16(acc[mt][nt][0], acc[mt][nt][1], acc[mt][nt][2], acc[mt][nt][3],
                            af[mt][0], af[mt][1], af[mt][2], af[mt][3],
                            bf[nt][0], bf[nt][1]);
        }
        __syncthreads();
        if (i + 2 < NI) {
            p_load(abase + s * P_AST * 4, g_xcat + (size_t)m0 * 768, 768, (i + 2) * 32, tid);
            p_load(bbase + s * P_AST * 4, g_wcat, 768, (i + 2) * 32, tid);
            asm volatile("cp.async.commit_group;" ::: "memory");
        }
    }
#pragma unroll
    for (int mt = 0; mt < 2; mt++)
#pragma unroll
        for (int nt = 0; nt < 8; nt++) {
            int r = m0 + wm * 32 + mt * 16 + lq;
            int c = wn * 64 + nt * 8 + lr * 2;
            *reinterpret_cast<float2*>(g_xp + (size_t)r * 128 + c) =
                make_float2(acc[mt][nt][0], acc[mt][nt][1]);
            *reinterpret_cast<float2*>(g_xp + (size_t)(r + 8) * 128 + c) =
                make_float2(acc[mt][nt][2], acc[mt][nt][3]);
        }
}

// ================= Kernel Z: z = adj @ y, fused h/MLP/softmax epilogue ====
#define ZA_ST 2560            // 128 rows * 20 u32 (fp16 A stage)
#define ZB_ST 2560            // 128 n-rows * 20 u32
#define NIZ   512
// epilogue smem offsets (floats)
#define H_OFF   0             // 128 x 132
#define H1_OFF  16896         // 128 x 68
#define W1T_OFF 25600         // 128 x 64
#define H2_OFF  33792         // 128 x 36
#define W2T_OFF 38400         // 64 x 32
#define W3T_OFF 40448         // 32 x 8
#define LG_OFF  40704         // 128 x 8
#define DEG_OFF 41728         // 128
#define Z_SMEM_FLOATS 41856

__global__ __launch_bounds__(512, 1)
void gemm_z(const float* __restrict__ adj,
            const float* __restrict__ W1, const float* __restrict__ b1,
            const float* __restrict__ W2, const float* __restrict__ b2,
            const float* __restrict__ W3, const float* __restrict__ b3,
            float* __restrict__ out) {
    extern __shared__ uint32_t smz[];
    uint32_t* Abuf = smz;
    uint32_t* Bbuf = smz + 2 * ZA_ST;
    float* pool = reinterpret_cast<float*>(smz);

    const int tid = threadIdx.x, wid = tid >> 5, lane = tid & 31;
    const int lq = lane >> 2, lr = lane & 3;
    const int gg = lane >> 3, cc = lane & 7;
    const int wm = wid & 3, wn = wid >> 2;      // 4M x 4N warps, tile 32x32
    const int m0 = blockIdx.x * 128;
    const uint32_t bbase = cvta_smem(Bbuf);

    float acc[2][4][4];
#pragma unroll
    for (int i = 0; i < 2; i++)
#pragma unroll
        for (int j = 0; j < 4; j++)
#pragma unroll
            for (int v = 0; v < 4; v++) acc[i][j][v] = 0.f;

    // B prologue (3 stages)
#pragma unroll
    for (int s = 0; s < 3; s++) {
        int n = tid >> 2, c4 = tid & 3;
        cp16(bbase + s * (ZB_ST * 4) + n * 80 + c4 * 16,
             g_yTh + (size_t)n * NROWS + s * 32 + c4 * 8);
        asm volatile("cp.async.commit_group;" ::: "memory");
    }

    const int rowA0 = wid * 8 + gg;
    float4 areg[2];
#pragma unroll
    for (int p = 0; p < 2; p++)
        areg[p] = *reinterpret_cast<const float4*>(
            adj + (size_t)(m0 + rowA0 + p * 4) * NROWS + cc * 4);
    float degp[2] = {0.f, 0.f};

#pragma unroll 1
    for (int i = 0; i < NIZ; i++) {
        const int sA = i & 1;
        const int sB = i % 3;
#pragma unroll
        for (int p = 0; p < 2; p++) {
            float4 v = areg[p];
            degp[p] += (v.x + v.y) + (v.z + v.w);
            __half2 h0 = __floats2half2_rn(v.x, v.y);
            __half2 h1 = __floats2half2_rn(v.z, v.w);
            uint32_t* dst = Abuf + sA * ZA_ST + (rowA0 + p * 4) * 20 + cc * 2;
            dst[0] = h2u(h0);
            dst[1] = h2u(h1);
        }
        if (i + 1 < NIZ) {
            int k0n = (i + 1) * 32;
#pragma unroll
            for (int p = 0; p < 2; p++)
                areg[p] = *reinterpret_cast<const float4*>(
                    adj + (size_t)(m0 + rowA0 + p * 4) * NROWS + k0n + cc * 4);
        }
        int rem = (NIZ - 1) - i;
        if (rem >= 2)      asm volatile("cp.async.wait_group 2;" ::: "memory");
        else if (rem == 1) asm volatile("cp.async.wait_group 1;" ::: "memory");
        else               asm volatile("cp.async.wait_group 0;" ::: "memory");
        __syncthreads();

        const uint32_t* As = Abuf + sA * ZA_ST;
        const uint32_t* Bs = Bbuf + sB * ZB_ST;
#pragma unroll
        for (int ks = 0; ks < 2; ks++) {
            uint32_t af[2][4];
#pragma unroll
            for (int mt = 0; mt < 2; mt++) {
                int b = (wm * 32 + mt * 16 + lq) * 20 + ks * 8 + lr;
                af[mt][0] = As[b]; af[mt][1] = As[b + 160];
                af[mt][2] = As[b + 4]; af[mt][3] = As[b + 164];
            }
            uint32_t bf[4][2];
#pragma unroll
            for (int nt = 0; nt < 4; nt++) {
                int b = (wn * 32 + nt * 8 + lq) * 20 + ks * 8 + lr;
                bf[nt][0] = Bs[b]; bf[nt][1] = Bs[b + 4];
            }
#pragma unroll
            for (int mt = 0; mt < 2; mt++)
#pragma unroll
                for (int nt = 0; nt < 4; nt++)
                    mma_f16(acc[mt][nt][0], acc[mt][nt][1], acc[mt][nt][2], acc[mt][nt][3],
                            af[mt][0], af[mt][1], af[mt][2], af[mt][3],
                            bf[nt][0], bf[nt][1]);
        }
        __syncthreads();
        if (i + 3 < NIZ) {
            int sN = (i + 3) % 3;
            int n = tid >> 2, c4 = tid & 3;
            cp16(bbase + sN * (ZB_ST * 4) + n * 80 + c4 * 16,
                 g_yTh + (size_t)n * NROWS + (i + 3) * 32 + c4 * 8);
            asm volatile("cp.async.commit_group;" ::: "memory");
        }
    }

    // ---- deg to smem ----
#pragma unroll
    for (int p = 0; p < 2; p++) {
        float d = degp[p];
#pragma unroll
        for (int off = 1; off < 8; off <<= 1)
            d += __shfl_xor_sync(0xffffffffu, d, off);
        if (cc == 0) pool[DEG_OFF + rowA0 + p * 4] = d + 1.0f;
    }
    __syncthreads();

    // ---- h = relu(xp + z/deg) -> smem ----
#pragma unroll
    for (int mt = 0; mt < 2; mt++) {
        int r = wm * 32 + mt * 16 + lq;
        float inv0 = 1.0f / pool[DEG_OFF + r];
        float inv1 = 1.0f / pool[DEG_OFF + r + 8];
#pragma unroll
        for (int nt = 0; nt < 4; nt++) {
            int c = wn * 32 + nt * 8 + lr * 2;
            float2 x0 = *reinterpret_cast<const float2*>(g_xp + (size_t)(m0 + r) * 128 + c);
            float2 x1 = *reinterpret_cast<const float2*>(g_xp + (size_t)(m0 + r + 8) * 128 + c);
            pool[H_OFF + r * 132 + c]           = fmaxf(x0.x + acc[mt][nt][0] * inv0, 0.f);
            pool[H_OFF + r * 132 + c + 1]       = fmaxf(x0.y + acc[mt][nt][1] * inv0, 0.f);
            pool[H_OFF + (r + 8) * 132 + c]     = fmaxf(x1.x + acc[mt][nt][2] * inv1, 0.f);
            pool[H_OFF + (r + 8) * 132 + c + 1] = fmaxf(x1.y + acc[mt][nt][3] * inv1, 0.f);
        }
    }
    // stage W1T/W2T/W3T
    for (int idx = tid; idx < 8192; idx += 512) {
        int j = idx >> 7, k = idx & 127;
        pool[W1T_OFF + k * 64 + j] = W1[idx];
    }
    for (int idx = tid; idx < 2048; idx += 512) {
        int j = idx >> 6, k = idx & 63;
        pool[W2T_OFF + k * 32 + j] = W2[idx];
    }
    if (tid < 256) {
        int j = tid >> 5, k = tid & 31;
        pool[W3T_OFF + k * 8 + j] = W3[tid];
    }
    __syncthreads();

    // ---- MLP1: h1 = lrelu(h @ W1^T + b1)  (128x64) ----
    {
        const int jg = tid & 15, rg = tid >> 4;    // 4 j x 4 r per thread
        float a[4][4];
#pragma unroll
        for (int jj = 0; jj < 4; jj++) {
            float bb = b1[jg * 4 + jj];
#pragma unroll
            for (int ri = 0; ri < 4; ri++) a[ri][jj] = bb;
        }
#pragma unroll 4
        for (int k = 0; k < 128; k++) {
            float4 wv = *reinterpret_cast<const float4*>(&pool[W1T_OFF + k * 64 + jg * 4]);
#pragma unroll
            for (int ri = 0; ri < 4; ri++) {
                float hv = pool[H_OFF + (rg * 4 + ri) * 132 + k];
                a[ri][0] += hv * wv.x; a[ri][1] += hv * wv.y;
                a[ri][2] += hv * wv.z; a[ri][3] += hv * wv.w;
            }
        }
#pragma unroll
        for (int ri = 0; ri < 4; ri++)
#pragma unroll
            for (int jj = 0; jj < 4; jj++) {
                float v = a[ri][jj];
                pool[H1_OFF + (rg * 4 + ri) * 68 + jg * 4 + jj] = (v > 0.f) ? v : 0.01f * v;
            }
    }
    __syncthreads();

    // ---- MLP2: h2 = lrelu(h1 @ W2^T + b2) (128x32) ----
#pragma unroll
    for (int ii = 0; ii < 8; ii++) {
        int o = tid + 512 * ii;
        int r = o >> 5, j = o & 31;
        float a = b2[j];
#pragma unroll 8
        for (int k = 0; k < 64; k++)
            a += pool[H1_OFF + r * 68 + k] * pool[W2T_OFF + k * 32 + j];
        pool[H2_OFF + r * 36 + j] = (a > 0.f) ? a : 0.01f * a;
    }
    __syncthreads();

    // ---- MLP3: logits (128x8) ----
#pragma unroll
    for (int ii = 0; ii < 2; ii++) {
        int o = tid + 512 * ii;
        int r = o >> 3, j = o & 7;
        float a = b3[j];
#pragma unroll
        for (int k = 0; k < 32; k++)
            a += pool[H2_OFF + r * 36 + k] * pool[W3T_OFF + k * 8 + j];
        pool[LG_OFF + r * 8 + j] = (a > 0.f) ? a : 0.01f * a;
    }
    __syncthreads();

    // ---- softmax + write ----
    if (tid < 128) {
        int r = tid;
        float vv[8], m = -1e30f;
#pragma unroll
        for (int c = 0; c < 8; c++) {
            vv[c] = pool[LG_OFF + r * 8 + c];
            m = fmaxf(m, vv[c]);
        }
        float s = 0.f;
#pragma unroll
        for (int c = 0; c < 8; c++) { vv[c] = expf(vv[c] - m); s += vv[c]; }
        float inv = 1.0f / s;
        float4 o0 = make_float4(vv[0] * inv, vv[1] * inv, vv[2] * inv, vv[3] * inv);
        float4 o1 = make_float4(vv[4] * inv, vv[5] * inv, vv[6] * inv, vv[7] * inv);
        *reinterpret_cast<float4*>(out + (size_t)(m0 + r) * 8)     = o0;
        *reinterpret_cast<float4*>(out + (size_t)(m0 + r) * 8 + 4) = o1;
    }
}

// ---------------- launch ----------------
extern "C" void kernel_launch(void* const* d_in, const int* in_sizes, int n_in,
                              void* d_out, int out_size) {
    const float* x   = (const float*)d_in[0];
    const float* adj = (const float*)d_in[1];
    const float* Wp  = (const float*)d_in[2];
    const float* W1  = (const float*)d_in[3];
    const float* b1  = (const float*)d_in[4];
    const float* W2  = (const float*)d_in[5];
    const float* b2  = (const float*)d_in[6];
    const float* W3  = (const float*)d_in[7];
    const float* b3  = (const float*)d_in[8];
    float* out = (float*)d_out;

    const int psm = 4 * P_AST * 4;                  // 40960
    const int zsm = Z_SMEM_FLOATS * 4;              // 167424
    cudaFuncSetAttribute(p2_yT, cudaFuncAttributeMaxDynamicSharedMemorySize, psm);
    cudaFuncSetAttribute(p3_xp, cudaFuncAttributeMaxDynamicSharedMemorySize, psm);
    cudaFuncSetAttribute(gemm_z, cudaFuncAttributeMaxDynamicSharedMemorySize, zsm);

    convert_x<<<4096, 256>>>(x);
    convert_w<<<256, 256>>>(Wp);
    p2_yT<<<128, 256, psm>>>();
    p3_xp<<<128, 256, psm>>>();
    gemm_z<<<128, 512, zsm>>>(adj, W1, b1, W2, b2, W3, b3, out);
}